// round 16
// baseline (speedup 1.0000x reference)
#include <cuda_runtime.h>
#include <cuda_bf16.h>
#include <cuda_fp16.h>
#include <cstdint>

#define BT 8192
#define T1 50
#define T2 100

static __device__ float g_seq1[BT * T1 * 128];
static __device__ uint32_t g_wihf[2 * 16 * 8 * 2 * 4 * 32];   // layer2 Wih frags
static __device__ uint32_t g_whhf[2 * 16 * 4 * 2 * 4 * 32];   // layer2 Whh frags
static __device__ uint32_t g_whh1f[2 * 16 * 4 * 2 * 4 * 32];  // layer1 Whh frags
static __device__ __half g_xg[2L * 128 * 50 * 16 * 1024];     // proj results (fp16, 420MB)

__device__ __forceinline__ float ftanh_(float x) {
    float e = __expf(-2.f * fabsf(x));
    float r = __fdividef(1.f - e, 1.f + e);
    return copysignf(r, x);
}
__device__ __forceinline__ float tanh_fast(float x) {
    float y;
    asm("tanh.approx.f32 %0, %1;" : "=f"(y) : "f"(x));
    return y;
}
__device__ __forceinline__ float sig_fast(float x) {
    return fmaf(tanh_fast(0.5f * x), 0.5f, 0.5f);
}
__device__ __forceinline__ uint32_t pack_bf2(float v0, float v1) {
    __nv_bfloat162 t = __floats2bfloat162_rn(v0, v1);
    return *(uint32_t*)&t;
}
__device__ __forceinline__ void split_pair(float v0, float v1, uint32_t& hi, uint32_t& lo) {
    __nv_bfloat16 h0 = __float2bfloat16_rn(v0), h1 = __float2bfloat16_rn(v1);
    hi = ((uint32_t)*(uint16_t*)&h1 << 16) | *(uint16_t*)&h0;
    lo = pack_bf2(v0 - __bfloat162float(h0), v1 - __bfloat162float(h1));
}
// paired B-frag word remap: old word p -> new word, so that (p, p+4) within an
// 8-word k-slice become adjacent (enables LDS.64 of both frag words).
__device__ __forceinline__ int pairw(int p) {
    return (p & ~7) + ((p & 3) << 1) + ((p & 7) >> 2);
}
#define MMA(c, a, b0, b1) \
    asm volatile("mma.sync.aligned.m16n8k16.row.col.f32.bf16.bf16.f32 " \
                 "{%0,%1,%2,%3},{%4,%5,%6,%7},{%8,%9},{%0,%1,%2,%3};" \
                 : "+f"((c)[0]), "+f"((c)[1]), "+f"((c)[2]), "+f"((c)[3]) \
                 : "r"((a)[0]), "r"((a)[1]), "r"((a)[2]), "r"((a)[3]), "r"(b0), "r"(b1))

// ===========================================================================
// k_prep (unchanged)
// ===========================================================================
__global__ void k_prep(const float* __restrict__ wf, const float* __restrict__ wb,
                       const float* __restrict__ hf, const float* __restrict__ hb,
                       const float* __restrict__ h1f, const float* __restrict__ h1b)
{
    const int gt = blockIdx.x * blockDim.x + threadIdx.x;
    const int nt = gridDim.x * blockDim.x;
    for (int e = gt; e < 2 * 16 * 8 * 4 * 32; e += nt) {
        int l = e & 31, r = (e >> 5) & 3, ks = (e >> 7) & 7, w = (e >> 10) & 15, d = e >> 14;
        const float* W = d ? wb : wf;
        int row = w * 16 + (l >> 2) + (r & 1) * 8;
        int col = ks * 16 + ((r >> 1) & 1) * 8 + (l & 3) * 2;
        uint32_t hi, lo;
        split_pair(W[row * 128 + col], W[row * 128 + col + 1], hi, lo);
        uint32_t base = (((d * 16 + w) * 8 + ks) * 2) * 128 + r * 32 + l;
        g_wihf[base] = hi; g_wihf[base + 128] = lo;
    }
    for (int e = gt; e < 2 * 16 * 4 * 4 * 32; e += nt) {
        int l = e & 31, r = (e >> 5) & 3, ks = (e >> 7) & 3, w = (e >> 9) & 15, d = e >> 13;
        int row = w * 16 + (l >> 2) + (r & 1) * 8;
        int col = ks * 16 + ((r >> 1) & 1) * 8 + (l & 3) * 2;
        uint32_t base = (((d * 16 + w) * 4 + ks) * 2) * 128 + r * 32 + l;
        uint32_t hi, lo;
        const float* W2 = d ? hb : hf;
        split_pair(W2[row * 64 + col], W2[row * 64 + col + 1], hi, lo);
        g_whhf[base] = hi; g_whhf[base + 128] = lo;
        const float* W1 = d ? h1b : h1f;
        split_pair(W1[row * 64 + col], W1[row * 64 + col + 1], hi, lo);
        g_whh1f[base] = hi; g_whh1f[base + 128] = lo;
    }
}

// ===========================================================================
// k_layer1: fc1 + BiLSTM layer 1 on mma.sync -> g_seq1 (paired hT, LDS.64)
// ===========================================================================
#define L1_H1  0                     // h1buf [64][52] fp32    = 13312B
#define L1_HTH 13312                 // hT hi [64][40] words   = 10240B
#define L1_HTL 23552                 // hT lo                  = 10240B
#define L1_GA  33792                 // gact [64][260] fp32    = 66560B
#define L1_SM  100352

__global__ __launch_bounds__(512, 1)
void k_layer1(const float* __restrict__ x,
              const float* __restrict__ fc1_w, const float* __restrict__ fc1_b,
              const float* __restrict__ wih_f, const float* __restrict__ b_f,
              const float* __restrict__ wih_b, const float* __restrict__ b_b)
{
    extern __shared__ char smc[];
    float*    h1  = (float*)(smc + L1_H1);
    uint32_t* hth = (uint32_t*)(smc + L1_HTH);
    uint32_t* htl = (uint32_t*)(smc + L1_HTL);
    float*    ga  = (float*)(smc + L1_GA);

    const int tid = threadIdx.x;
    const int w   = tid >> 5, lid = tid & 31;
    const int grp = lid >> 2, tk = lid & 3;
    const int j = tid & 63, q = tid >> 6;
    const int blk = blockIdx.x;

    for (int idx = tid; idx < 64 * T1; idx += 512) {
        int s = idx / T1, t = idx - s * T1;
        const float* xr = x + (size_t)(blk * 64 + s) * 20;
        const float* wr = fc1_w + t * 20;
        float acc = __ldg(&fc1_b[t]);
        #pragma unroll
        for (int i = 0; i < 20; i++) acc = fmaf(__ldg(xr + i), __ldg(wr + i), acc);
        h1[s * 52 + t] = acc;
    }

    const int hwj = pairw(j >> 1) * 2 + (j & 1);   // per-thread halfword offset in a row

    for (int d = 0; d < 2; d++) {
        const float* bg  = d ? b_b : b_f;
        const float* wih = d ? wih_b : wih_f;
        const float bv0 = __ldg(&bg[w * 16 + grp]);
        const float bv1 = __ldg(&bg[w * 16 + grp + 8]);
        const float wi0 = __ldg(&wih[w * 16 + grp]);
        const float wi1 = __ldg(&wih[w * 16 + grp + 8]);

        uint32_t wa[32];
        {
            const uint32_t* hp = g_whh1f + (d * 16 + w) * 4 * 256 + lid;
            #pragma unroll
            for (int ks = 0; ks < 4; ks++)
                #pragma unroll
                for (int tm = 0; tm < 2; tm++)
                    #pragma unroll
                    for (int r = 0; r < 4; r++)
                        wa[(ks * 2 + tm) * 4 + r] = __ldg(hp + (ks * 2 + tm) * 128 + r * 32);
        }

        __syncthreads();
        for (int p = tid; p < 5120; p += 512) hth[p] = 0u;   // hth+htl contiguous
        float c8[8];
        #pragma unroll
        for (int i = 0; i < 8; i++) c8[i] = 0.f;
        __syncthreads();

        for (int tt = 0; tt < T1; tt++) {
            const int t = d ? (T1 - 1 - tt) : tt;

            float cc[8][4];
            #pragma unroll
            for (int n = 0; n < 8; n++) {
                int s0 = n * 8 + 2 * tk;
                float xa = h1[s0 * 52 + t], xb = h1[(s0 + 1) * 52 + t];
                cc[n][0] = fmaf(wi0, xa, bv0);
                cc[n][1] = fmaf(wi0, xb, bv0);
                cc[n][2] = fmaf(wi1, xa, bv1);
                cc[n][3] = fmaf(wi1, xb, bv1);
            }

            #pragma unroll
            for (int ks = 0; ks < 4; ks++) {
                #pragma unroll
                for (int n = 0; n < 8; n++) {
                    int wd = (n * 8 + grp) * 40 + ks * 8 + tk * 2;
                    uint2 vh = *(const uint2*)(hth + wd);
                    uint2 vl = *(const uint2*)(htl + wd);
                    MMA(cc[n], &wa[(ks * 2 + 0) * 4], vh.x, vh.y);
                    MMA(cc[n], &wa[(ks * 2 + 0) * 4], vl.x, vl.y);
                    MMA(cc[n], &wa[(ks * 2 + 1) * 4], vh.x, vh.y);
                }
            }

            #pragma unroll
            for (int n = 0; n < 8; n++) {
                int s0 = n * 8 + 2 * tk, gcol = w * 16 + grp;
                ga[s0 * 260 + gcol]           = cc[n][0];
                ga[(s0 + 1) * 260 + gcol]     = cc[n][1];
                ga[s0 * 260 + gcol + 8]       = cc[n][2];
                ga[(s0 + 1) * 260 + gcol + 8] = cc[n][3];
            }
            __syncthreads();

            #pragma unroll
            for (int si = 0; si < 8; si++) {
                const int s = q + si * 8;
                float gi = ga[s * 260 + j],       gf = ga[s * 260 + 64 + j];
                float gg = ga[s * 260 + 128 + j], go = ga[s * 260 + 192 + j];
                float c = fmaf(sig_fast(gf), c8[si], sig_fast(gi) * tanh_fast(gg));
                c8[si] = c;
                float h = sig_fast(go) * tanh_fast(c);
                g_seq1[((size_t)(blk * 64 + s) * T1 + t) * 128 + d * 64 + j] = h;
                __nv_bfloat16 hh = __float2bfloat16_rn(h);
                __nv_bfloat16 hl = __float2bfloat16_rn(h - __bfloat162float(hh));
                ((__nv_bfloat16*)hth)[s * 80 + hwj] = hh;
                ((__nv_bfloat16*)htl)[s * 80 + hwj] = hl;
            }
            __syncthreads();
        }
    }
}

// ===========================================================================
// k_proj v4: same as v3 but fp16 output (halved DRAM traffic)
// ===========================================================================
#define PJ_W  0
#define PJ_X  131072
#define PJ_SM (131072 + 69632)

__global__ __launch_bounds__(512, 1)
void k_proj(const float* __restrict__ b2_f, const float* __restrict__ b2_b)
{
    extern __shared__ char smc[];
    uint32_t* wsm = (uint32_t*)(smc + PJ_W);

    const int tid = threadIdx.x;
    const int w   = tid >> 5, lid = tid & 31;
    const int grp = lid >> 2, tk = lid & 3;
    const int bi  = blockIdx.x;
    const int d   = bi >> 8, blk = (bi >> 1) & 127, half = bi & 1;
    const int m0  = half * 25;

    const float* bg = d ? b2_b : b2_f;
    const float bv0 = __ldg(&bg[w * 16 + grp]);
    const float bv1 = __ldg(&bg[w * 16 + grp + 8]);

    {
        const uint32_t* src = g_wihf + d * 32768;
        for (int p = tid; p < 32768; p += 512) wsm[p] = __ldg(src + p);
    }
    const uint32_t* wp = wsm + w * 2048 + lid;

    const int srow = tid >> 3, f0 = (tid & 7) * 16;
    const int wbase = srow * 68 + (f0 >> 1);

    float4 xr[4];
    {
        const float4* p = (const float4*)(g_seq1 +
            ((size_t)(blk * 64 + srow) * T1 + m0) * 128 + f0);
        #pragma unroll
        for (int i = 0; i < 4; i++) xr[i] = __ldg(p + i);
    }
    __syncthreads();

    for (int mi = 0; mi < 25; mi++) {
        const int m = m0 + mi;
        uint32_t* xth = (uint32_t*)(smc + PJ_X + (mi & 1) * 34816);
        uint32_t* xtl = xth + 4352;

        #pragma unroll
        for (int i = 0; i < 4; i++) {
            uint32_t h0, l0, h1, l1;
            split_pair(xr[i].x, xr[i].y, h0, l0);
            split_pair(xr[i].z, xr[i].w, h1, l1);
            xth[wbase + i * 2] = h0; xth[wbase + i * 2 + 1] = h1;
            xtl[wbase + i * 2] = l0; xtl[wbase + i * 2 + 1] = l1;
        }
        __syncthreads();

        if (mi < 24) {
            const float4* p = (const float4*)(g_seq1 +
                ((size_t)(blk * 64 + srow) * T1 + (m + 1)) * 128 + f0);
            #pragma unroll
            for (int i = 0; i < 4; i++) xr[i] = __ldg(p + i);
        }

        float cc[8][4];
        #pragma unroll
        for (int n = 0; n < 8; n++) {
            cc[n][0] = bv0; cc[n][1] = bv0; cc[n][2] = bv1; cc[n][3] = bv1;
        }
        for (int ks = 0; ks < 8; ks++) {
            uint32_t ah[4], al[4];
            #pragma unroll
            for (int r = 0; r < 4; r++) {
                ah[r] = wp[ks * 256 + r * 32];
                al[r] = wp[ks * 256 + 128 + r * 32];
            }
            #pragma unroll
            for (int n = 0; n < 8; n++) {
                int wd = (n * 8 + grp) * 68 + ks * 8 + tk;
                uint32_t bh0 = xth[wd], bh1 = xth[wd + 4];
                uint32_t bl0 = xtl[wd], bl1 = xtl[wd + 4];
                MMA(cc[n], ah, bh0, bh1);
                MMA(cc[n], ah, bl0, bl1);
                MMA(cc[n], al, bh0, bh1);
            }
        }
        __half* op = g_xg + ((((size_t)(d * 128 + blk) * 50 + m) * 16 + w) * 8) * 128 + lid * 4;
        #pragma unroll
        for (int n = 0; n < 8; n++) {
            __half2 a = __floats2half2_rn(cc[n][0], cc[n][1]);
            __half2 b = __floats2half2_rn(cc[n][2], cc[n][3]);
            uint2 v;
            v.x = *(uint32_t*)&a; v.y = *(uint32_t*)&b;
            *(uint2*)(op + n * 128) = v;
        }
        __syncthreads();
    }
}

// ===========================================================================
// k_layer2 v3: half-split pipeline + paired hT (LDS.64) + fp16 xg
// ===========================================================================
#define L2_HTA 0            // A hi: 32 rows x 40 words = 5120B
#define L2_HLA 5120
#define L2_HTB 10240
#define L2_HLB 15360
#define L2_GA  20480        // 32*260*4 = 33280
#define L2_HBF 53760        // 32*68*4  = 8704
#define L2_OA  62464        // 64*100*4 = 25600
#define L2_SM  88064

__global__ __launch_bounds__(512, 1)
void k_layer2(const float* __restrict__ fc2_w, const float* __restrict__ fc2_b,
              float* __restrict__ out)
{
    extern __shared__ char smc[];
    uint32_t* hthA = (uint32_t*)(smc + L2_HTA);
    uint32_t* htlA = (uint32_t*)(smc + L2_HLA);
    uint32_t* hthB = (uint32_t*)(smc + L2_HTB);
    uint32_t* htlB = (uint32_t*)(smc + L2_HLB);
    float*    ga   = (float*)(smc + L2_GA);
    float*    hbf  = (float*)(smc + L2_HBF);
    float*    oa   = (float*)(smc + L2_OA);

    const int tid = threadIdx.x;
    const int w   = tid >> 5, lid = tid & 31;
    const int grp = lid >> 2, tk = lid & 3;
    const int j = tid & 63, q = tid >> 6;
    const int blk = blockIdx.x;
    const float fc2bv = __ldg(fc2_b);
    const int hwj = pairw(j >> 1) * 2 + (j & 1);

    for (int d = 0; d < 2; d++) {
        const float fwa = __ldg(&fc2_w[d * 64 + lid]);
        const float fwb = __ldg(&fc2_w[d * 64 + 32 + lid]);

        uint32_t wa[32];
        {
            const uint32_t* hp = g_whhf + (d * 16 + w) * 4 * 256 + lid;
            #pragma unroll
            for (int ks = 0; ks < 4; ks++)
                #pragma unroll
                for (int tm = 0; tm < 2; tm++)
                    #pragma unroll
                    for (int r = 0; r < 4; r++)
                        wa[(ks * 2 + tm) * 4 + r] = __ldg(hp + (ks * 2 + tm) * 128 + r * 32);
        }

        __syncthreads();
        for (int p = tid; p < 5120; p += 512) hthA[p] = 0u;   // zeros all 4 tiles
        float c8A[4] = {0.f, 0.f, 0.f, 0.f};
        float c8B[4] = {0.f, 0.f, 0.f, 0.f};

        float xgA[16], xgB[16];
        {
            const int m0 = d ? 49 : 0;
            const __half* xp = g_xg + ((((size_t)(d * 128 + blk) * 50 + m0) * 16 + w) * 8) * 128 + lid * 4;
            #pragma unroll
            for (int nl = 0; nl < 4; nl++) {
                uint2 v = __ldg((const uint2*)(xp + nl * 128));
                float2 fa = __half22float2(*(__half2*)&v.x);
                float2 fb = __half22float2(*(__half2*)&v.y);
                xgA[nl * 4 + 0] = fa.x; xgA[nl * 4 + 1] = fa.y;
                xgA[nl * 4 + 2] = fb.x; xgA[nl * 4 + 3] = fb.y;
                uint2 u = __ldg((const uint2*)(xp + (4 + nl) * 128));
                float2 ga2 = __half22float2(*(__half2*)&u.x);
                float2 gb2 = __half22float2(*(__half2*)&u.y);
                xgB[nl * 4 + 0] = ga2.x; xgB[nl * 4 + 1] = ga2.y;
                xgB[nl * 4 + 2] = gb2.x; xgB[nl * 4 + 3] = gb2.y;
            }
        }
        __syncthreads();

        float cc[4][4];
        for (int tt = 0; tt < T2; tt++) {
            const int t  = d ? (T2 - 1 - tt) : tt;
            const int tp = d ? (t + 1) : (t - 1);
            const bool pf = (tt & 1) && (tt < 99);
            const int mn = pf ? (d ? ((t >> 1) - 1) : ((t >> 1) + 1)) : 0;
            const __half* xpn = g_xg + ((((size_t)(d * 128 + blk) * 50 + mn) * 16 + w) * 8) * 128 + lid * 4;

            // ---- Phase A: MMA half A (step tt) ----
            #pragma unroll
            for (int nl = 0; nl < 4; nl++)
                #pragma unroll
                for (int r = 0; r < 4; r++) cc[nl][r] = xgA[nl * 4 + r];
            if (pf) {
                #pragma unroll
                for (int nl = 0; nl < 4; nl++) {
                    uint2 v = __ldg((const uint2*)(xpn + nl * 128));
                    float2 fa = __half22float2(*(__half2*)&v.x);
                    float2 fb = __half22float2(*(__half2*)&v.y);
                    xgA[nl * 4 + 0] = fa.x; xgA[nl * 4 + 1] = fa.y;
                    xgA[nl * 4 + 2] = fb.x; xgA[nl * 4 + 3] = fb.y;
                }
            }
            #pragma unroll
            for (int ks = 0; ks < 4; ks++) {
                #pragma unroll
                for (int nl = 0; nl < 4; nl++) {
                    int wd = (nl * 8 + grp) * 40 + ks * 8 + tk * 2;
                    uint2 vh = *(const uint2*)(hthA + wd);
                    uint2 vl = *(const uint2*)(htlA + wd);
                    MMA(cc[nl], &wa[(ks * 2 + 0) * 4], vh.x, vh.y);
                    MMA(cc[nl], &wa[(ks * 2 + 0) * 4], vl.x, vl.y);
                    MMA(cc[nl], &wa[(ks * 2 + 1) * 4], vh.x, vh.y);
                }
            }

            // ---- Phase B: epilogue half B (step tt-1) ----
            if (tt > 0) {
                #pragma unroll
                for (int si = 0; si < 4; si++) {
                    const int sl = q + si * 8;
                    float gi = ga[sl * 260 + j],       gf = ga[sl * 260 + 64 + j];
                    float gg = ga[sl * 260 + 128 + j], go = ga[sl * 260 + 192 + j];
                    float c = fmaf(sig_fast(gf), c8B[si], sig_fast(gi) * tanh_fast(gg));
                    c8B[si] = c;
                    float h = sig_fast(go) * tanh_fast(c);
                    hbf[sl * 68 + j] = h;
                    __nv_bfloat16 hh = __float2bfloat16_rn(h);
                    __nv_bfloat16 hl = __float2bfloat16_rn(h - __bfloat162float(hh));
                    ((__nv_bfloat16*)hthB)[sl * 80 + hwj] = hh;
                    ((__nv_bfloat16*)htlB)[sl * 80 + hwj] = hl;
                }
            }
            __syncthreads();   // bar1

            // ---- Phase C: fc2 half B (tt-1) + scatter A ----
            if (tt > 0) {
                #pragma unroll
                for (int si2 = 0; si2 < 2; si2++) {
                    const int sl = w * 2 + si2, s = 32 + sl;
                    float pm = hbf[sl * 68 + lid] * fwa + hbf[sl * 68 + 32 + lid] * fwb;
                    #pragma unroll
                    for (int o = 16; o > 0; o >>= 1)
                        pm += __shfl_down_sync(0xffffffffu, pm, o);
                    if (lid == 0) {
                        if (d == 0) oa[s * 100 + tp] = pm;
                        else out[(size_t)(blk * 64 + s) * T2 + tp] = ftanh_(oa[s * 100 + tp] + pm + fc2bv);
                    }
                }
            }
            #pragma unroll
            for (int nl = 0; nl < 4; nl++) {
                int sl0 = nl * 8 + 2 * tk, gcol = w * 16 + grp;
                ga[sl0 * 260 + gcol]           = cc[nl][0];
                ga[(sl0 + 1) * 260 + gcol]     = cc[nl][1];
                ga[sl0 * 260 + gcol + 8]       = cc[nl][2];
                ga[(sl0 + 1) * 260 + gcol + 8] = cc[nl][3];
            }
            __syncthreads();   // bar2

            // ---- Phase D: MMA half B (step tt) ----
            #pragma unroll
            for (int nl = 0; nl < 4; nl++)
                #pragma unroll
                for (int r = 0; r < 4; r++) cc[nl][r] = xgB[nl * 4 + r];
            if (pf) {
                #pragma unroll
                for (int nl = 0; nl < 4; nl++) {
                    uint2 u = __ldg((const uint2*)(xpn + (4 + nl) * 128));
                    float2 ga2 = __half22float2(*(__half2*)&u.x);
                    float2 gb2 = __half22float2(*(__half2*)&u.y);
                    xgB[nl * 4 + 0] = ga2.x; xgB[nl * 4 + 1] = ga2.y;
                    xgB[nl * 4 + 2] = gb2.x; xgB[nl * 4 + 3] = gb2.y;
                }
            }
            #pragma unroll
            for (int ks = 0; ks < 4; ks++) {
                #pragma unroll
                for (int nl = 0; nl < 4; nl++) {
                    int wd = (nl * 8 + grp) * 40 + ks * 8 + tk * 2;
                    uint2 vh = *(const uint2*)(hthB + wd);
                    uint2 vl = *(const uint2*)(htlB + wd);
                    MMA(cc[nl], &wa[(ks * 2 + 0) * 4], vh.x, vh.y);
                    MMA(cc[nl], &wa[(ks * 2 + 0) * 4], vl.x, vl.y);
                    MMA(cc[nl], &wa[(ks * 2 + 1) * 4], vh.x, vh.y);
                }
            }

            // ---- Phase E: epilogue half A (step tt) ----
            #pragma unroll
            for (int si = 0; si < 4; si++) {
                const int sl = q + si * 8;
                float gi = ga[sl * 260 + j],       gf = ga[sl * 260 + 64 + j];
                float gg = ga[sl * 260 + 128 + j], go = ga[sl * 260 + 192 + j];
                float c = fmaf(sig_fast(gf), c8A[si], sig_fast(gi) * tanh_fast(gg));
                c8A[si] = c;
                float h = sig_fast(go) * tanh_fast(c);
                hbf[sl * 68 + j] = h;
                __nv_bfloat16 hh = __float2bfloat16_rn(h);
                __nv_bfloat16 hl = __float2bfloat16_rn(h - __bfloat162float(hh));
                ((__nv_bfloat16*)hthA)[sl * 80 + hwj] = hh;
                ((__nv_bfloat16*)htlA)[sl * 80 + hwj] = hl;
            }
            __syncthreads();   // bar3

            // ---- Phase F: fc2 half A (tt) + scatter B ----
            #pragma unroll
            for (int si2 = 0; si2 < 2; si2++) {
                const int sl = w * 2 + si2, s = sl;
                float pm = hbf[sl * 68 + lid] * fwa + hbf[sl * 68 + 32 + lid] * fwb;
                #pragma unroll
                for (int o = 16; o > 0; o >>= 1)
                    pm += __shfl_down_sync(0xffffffffu, pm, o);
                if (lid == 0) {
                    if (d == 0) oa[s * 100 + t] = pm;
                    else out[(size_t)(blk * 64 + s) * T2 + t] = ftanh_(oa[s * 100 + t] + pm + fc2bv);
                }
            }
            #pragma unroll
            for (int nl = 0; nl < 4; nl++) {
                int sl0 = nl * 8 + 2 * tk, gcol = w * 16 + grp;
                ga[sl0 * 260 + gcol]           = cc[nl][0];
                ga[(sl0 + 1) * 260 + gcol]     = cc[nl][1];
                ga[sl0 * 260 + gcol + 8]       = cc[nl][2];
                ga[(sl0 + 1) * 260 + gcol + 8] = cc[nl][3];
            }
            __syncthreads();   // bar4
        }

        // ---- drain: epilogue + fc2 for half B, last step ----
        {
            const int tl = d ? 0 : (T2 - 1);
            #pragma unroll
            for (int si = 0; si < 4; si++) {
                const int sl = q + si * 8;
                float gi = ga[sl * 260 + j],       gf = ga[sl * 260 + 64 + j];
                float gg = ga[sl * 260 + 128 + j], go = ga[sl * 260 + 192 + j];
                float c = fmaf(sig_fast(gf), c8B[si], sig_fast(gi) * tanh_fast(gg));
                c8B[si] = c;
                float h = sig_fast(go) * tanh_fast(c);
                hbf[sl * 68 + j] = h;
            }
            __syncthreads();
            #pragma unroll
            for (int si2 = 0; si2 < 2; si2++) {
                const int sl = w * 2 + si2, s = 32 + sl;
                float pm = hbf[sl * 68 + lid] * fwa + hbf[sl * 68 + 32 + lid] * fwb;
                #pragma unroll
                for (int o = 16; o > 0; o >>= 1)
                    pm += __shfl_down_sync(0xffffffffu, pm, o);
                if (lid == 0) {
                    if (d == 0) oa[s * 100 + tl] = pm;
                    else out[(size_t)(blk * 64 + s) * T2 + tl] = ftanh_(oa[s * 100 + tl] + pm + fc2bv);
                }
            }
            __syncthreads();
        }
    }
}

// ---------------------------------------------------------------------------
extern "C" void kernel_launch(void* const* d_in, const int* in_sizes, int n_in,
                              void* d_out, int out_size)
{
    const float* x    = (const float*)d_in[0];
    const float* fc1w = (const float*)d_in[1];
    const float* fc1b = (const float*)d_in[2];
    const float* r1wf = (const float*)d_in[3];
    const float* r1hf = (const float*)d_in[4];
    const float* r1bf = (const float*)d_in[5];
    const float* r1wb = (const float*)d_in[6];
    const float* r1hb = (const float*)d_in[7];
    const float* r1bb = (const float*)d_in[8];
    const float* r2wf = (const float*)d_in[9];
    const float* r2hf = (const float*)d_in[10];
    const float* r2bf = (const float*)d_in[11];
    const float* r2wb = (const float*)d_in[12];
    const float* r2hb = (const float*)d_in[13];
    const float* r2bb = (const float*)d_in[14];
    const float* fc2w = (const float*)d_in[15];
    const float* fc2b = (const float*)d_in[16];
    float* out = (float*)d_out;

    cudaFuncSetAttribute(k_layer1, cudaFuncAttributeMaxDynamicSharedMemorySize, L1_SM);
    cudaFuncSetAttribute(k_proj,   cudaFuncAttributeMaxDynamicSharedMemorySize, PJ_SM);
    cudaFuncSetAttribute(k_layer2, cudaFuncAttributeMaxDynamicSharedMemorySize, L2_SM);

    k_prep<<<64, 256>>>(r2wf, r2wb, r2hf, r2hb, r1hf, r1hb);
    k_layer1<<<128, 512, L1_SM>>>(x, fc1w, fc1b, r1wf, r1bf, r1wb, r1bb);
    k_proj<<<512, 512, PJ_SM>>>(r2bf, r2bb);
    k_layer2<<<128, 512, L2_SM>>>(fc2w, fc2b, out);
}

// round 17
// speedup vs baseline: 1.4902x; 1.4902x over previous
#include <cuda_runtime.h>
#include <cuda_bf16.h>
#include <cuda_fp16.h>
#include <cstdint>

#define BT 8192
#define T1 50
#define T2 100

static __device__ float g_seq1[BT * T1 * 128];
static __device__ uint32_t g_wihf[2 * 16 * 8 * 2 * 4 * 32];   // layer2 Wih frags
static __device__ uint32_t g_whhf[2 * 16 * 4 * 2 * 4 * 32];   // layer2 Whh frags
static __device__ uint32_t g_whh1f[2 * 16 * 4 * 2 * 4 * 32];  // layer1 Whh frags
static __device__ __half g_xg[2L * 128 * 50 * 16 * 1024];     // proj results (fp16, 420MB)

__device__ __forceinline__ float ftanh_(float x) {
    float e = __expf(-2.f * fabsf(x));
    float r = __fdividef(1.f - e, 1.f + e);
    return copysignf(r, x);
}
__device__ __forceinline__ float tanh_fast(float x) {
    float y;
    asm("tanh.approx.f32 %0, %1;" : "=f"(y) : "f"(x));
    return y;
}
__device__ __forceinline__ float sig_fast(float x) {
    return fmaf(tanh_fast(0.5f * x), 0.5f, 0.5f);
}
__device__ __forceinline__ uint32_t pack_bf2(float v0, float v1) {
    __nv_bfloat162 t = __floats2bfloat162_rn(v0, v1);
    return *(uint32_t*)&t;
}
__device__ __forceinline__ void split_pair(float v0, float v1, uint32_t& hi, uint32_t& lo) {
    __nv_bfloat16 h0 = __float2bfloat16_rn(v0), h1 = __float2bfloat16_rn(v1);
    hi = ((uint32_t)*(uint16_t*)&h1 << 16) | *(uint16_t*)&h0;
    lo = pack_bf2(v0 - __bfloat162float(h0), v1 - __bfloat162float(h1));
}
#define MMA(c, a, b0, b1) \
    asm volatile("mma.sync.aligned.m16n8k16.row.col.f32.bf16.bf16.f32 " \
                 "{%0,%1,%2,%3},{%4,%5,%6,%7},{%8,%9},{%0,%1,%2,%3};" \
                 : "+f"((c)[0]), "+f"((c)[1]), "+f"((c)[2]), "+f"((c)[3]) \
                 : "r"((a)[0]), "r"((a)[1]), "r"((a)[2]), "r"((a)[3]), "r"(b0), "r"(b1))

// ===========================================================================
// k_prep (unchanged)
// ===========================================================================
__global__ void k_prep(const float* __restrict__ wf, const float* __restrict__ wb,
                       const float* __restrict__ hf, const float* __restrict__ hb,
                       const float* __restrict__ h1f, const float* __restrict__ h1b)
{
    const int gt = blockIdx.x * blockDim.x + threadIdx.x;
    const int nt = gridDim.x * blockDim.x;
    for (int e = gt; e < 2 * 16 * 8 * 4 * 32; e += nt) {
        int l = e & 31, r = (e >> 5) & 3, ks = (e >> 7) & 7, w = (e >> 10) & 15, d = e >> 14;
        const float* W = d ? wb : wf;
        int row = w * 16 + (l >> 2) + (r & 1) * 8;
        int col = ks * 16 + ((r >> 1) & 1) * 8 + (l & 3) * 2;
        uint32_t hi, lo;
        split_pair(W[row * 128 + col], W[row * 128 + col + 1], hi, lo);
        uint32_t base = (((d * 16 + w) * 8 + ks) * 2) * 128 + r * 32 + l;
        g_wihf[base] = hi; g_wihf[base + 128] = lo;
    }
    for (int e = gt; e < 2 * 16 * 4 * 4 * 32; e += nt) {
        int l = e & 31, r = (e >> 5) & 3, ks = (e >> 7) & 3, w = (e >> 9) & 15, d = e >> 13;
        int row = w * 16 + (l >> 2) + (r & 1) * 8;
        int col = ks * 16 + ((r >> 1) & 1) * 8 + (l & 3) * 2;
        uint32_t base = (((d * 16 + w) * 4 + ks) * 2) * 128 + r * 32 + l;
        uint32_t hi, lo;
        const float* W2 = d ? hb : hf;
        split_pair(W2[row * 64 + col], W2[row * 64 + col + 1], hi, lo);
        g_whhf[base] = hi; g_whhf[base + 128] = lo;
        const float* W1 = d ? h1b : h1f;
        split_pair(W1[row * 64 + col], W1[row * 64 + col + 1], hi, lo);
        g_whh1f[base] = hi; g_whh1f[base + 128] = lo;
    }
}

// ===========================================================================
// k_layer1 (mma, round-14/15 validated version — stride-36 hT, LDS.32)
// ===========================================================================
#define L1_H1  0
#define L1_HTH 13312
#define L1_HTL 22528
#define L1_GA  31744
#define L1_SM  98304

__global__ __launch_bounds__(512, 1)
void k_layer1(const float* __restrict__ x,
              const float* __restrict__ fc1_w, const float* __restrict__ fc1_b,
              const float* __restrict__ wih_f, const float* __restrict__ b_f,
              const float* __restrict__ wih_b, const float* __restrict__ b_b)
{
    extern __shared__ char smc[];
    float*    h1  = (float*)(smc + L1_H1);
    uint32_t* hth = (uint32_t*)(smc + L1_HTH);
    uint32_t* htl = (uint32_t*)(smc + L1_HTL);
    float*    ga  = (float*)(smc + L1_GA);

    const int tid = threadIdx.x;
    const int w   = tid >> 5, lid = tid & 31;
    const int grp = lid >> 2, tk = lid & 3;
    const int j = tid & 63, q = tid >> 6;
    const int blk = blockIdx.x;

    for (int idx = tid; idx < 64 * T1; idx += 512) {
        int s = idx / T1, t = idx - s * T1;
        const float* xr = x + (size_t)(blk * 64 + s) * 20;
        const float* wr = fc1_w + t * 20;
        float acc = __ldg(&fc1_b[t]);
        #pragma unroll
        for (int i = 0; i < 20; i++) acc = fmaf(__ldg(xr + i), __ldg(wr + i), acc);
        h1[s * 52 + t] = acc;
    }

    for (int d = 0; d < 2; d++) {
        const float* bg  = d ? b_b : b_f;
        const float* wih = d ? wih_b : wih_f;
        const float bv0 = __ldg(&bg[w * 16 + grp]);
        const float bv1 = __ldg(&bg[w * 16 + grp + 8]);
        const float wi0 = __ldg(&wih[w * 16 + grp]);
        const float wi1 = __ldg(&wih[w * 16 + grp + 8]);

        uint32_t wa[32];
        {
            const uint32_t* hp = g_whh1f + (d * 16 + w) * 4 * 256 + lid;
            #pragma unroll
            for (int ks = 0; ks < 4; ks++)
                #pragma unroll
                for (int tm = 0; tm < 2; tm++)
                    #pragma unroll
                    for (int r = 0; r < 4; r++)
                        wa[(ks * 2 + tm) * 4 + r] = __ldg(hp + (ks * 2 + tm) * 128 + r * 32);
        }

        __syncthreads();
        for (int p = tid; p < 4608; p += 512) hth[p] = 0u;
        float c8[8];
        #pragma unroll
        for (int i = 0; i < 8; i++) c8[i] = 0.f;
        __syncthreads();

        for (int tt = 0; tt < T1; tt++) {
            const int t = d ? (T1 - 1 - tt) : tt;

            float cc[8][4];
            #pragma unroll
            for (int n = 0; n < 8; n++) {
                int s0 = n * 8 + 2 * tk;
                float xa = h1[s0 * 52 + t], xb = h1[(s0 + 1) * 52 + t];
                cc[n][0] = fmaf(wi0, xa, bv0);
                cc[n][1] = fmaf(wi0, xb, bv0);
                cc[n][2] = fmaf(wi1, xa, bv1);
                cc[n][3] = fmaf(wi1, xb, bv1);
            }

            #pragma unroll
            for (int ks = 0; ks < 4; ks++) {
                #pragma unroll
                for (int n = 0; n < 8; n++) {
                    int wd = (n * 8 + grp) * 36 + ks * 8 + tk;
                    uint32_t bh0 = hth[wd], bh1 = hth[wd + 4];
                    uint32_t bl0 = htl[wd], bl1 = htl[wd + 4];
                    MMA(cc[n], &wa[(ks * 2 + 0) * 4], bh0, bh1);
                    MMA(cc[n], &wa[(ks * 2 + 0) * 4], bl0, bl1);
                    MMA(cc[n], &wa[(ks * 2 + 1) * 4], bh0, bh1);
                }
            }

            #pragma unroll
            for (int n = 0; n < 8; n++) {
                int s0 = n * 8 + 2 * tk, gcol = w * 16 + grp;
                ga[s0 * 260 + gcol]           = cc[n][0];
                ga[(s0 + 1) * 260 + gcol]     = cc[n][1];
                ga[s0 * 260 + gcol + 8]       = cc[n][2];
                ga[(s0 + 1) * 260 + gcol + 8] = cc[n][3];
            }
            __syncthreads();

            #pragma unroll
            for (int si = 0; si < 8; si++) {
                const int s = q + si * 8;
                float gi = ga[s * 260 + j],       gf = ga[s * 260 + 64 + j];
                float gg = ga[s * 260 + 128 + j], go = ga[s * 260 + 192 + j];
                float c = fmaf(sig_fast(gf), c8[si], sig_fast(gi) * tanh_fast(gg));
                c8[si] = c;
                float h = sig_fast(go) * tanh_fast(c);
                g_seq1[((size_t)(blk * 64 + s) * T1 + t) * 128 + d * 64 + j] = h;
                __nv_bfloat16 hh = __float2bfloat16_rn(h);
                __nv_bfloat16 hl = __float2bfloat16_rn(h - __bfloat162float(hh));
                ((__nv_bfloat16*)hth)[s * 72 + j] = hh;
                ((__nv_bfloat16*)htl)[s * 72 + j] = hl;
            }
            __syncthreads();
        }
    }
}

// ===========================================================================
// k_proj v4: round-13 core, fp16 output (halved DRAM write traffic)
// ===========================================================================
#define PJ_W  0
#define PJ_X  131072
#define PJ_SM (131072 + 69632)

__global__ __launch_bounds__(512, 1)
void k_proj(const float* __restrict__ b2_f, const float* __restrict__ b2_b)
{
    extern __shared__ char smc[];
    uint32_t* wsm = (uint32_t*)(smc + PJ_W);

    const int tid = threadIdx.x;
    const int w   = tid >> 5, lid = tid & 31;
    const int grp = lid >> 2, tk = lid & 3;
    const int bi  = blockIdx.x;
    const int d   = bi >> 8, blk = (bi >> 1) & 127, half = bi & 1;
    const int m0  = half * 25;

    const float* bg = d ? b2_b : b2_f;
    const float bv0 = __ldg(&bg[w * 16 + grp]);
    const float bv1 = __ldg(&bg[w * 16 + grp + 8]);

    {
        const uint32_t* src = g_wihf + d * 32768;
        for (int p = tid; p < 32768; p += 512) wsm[p] = __ldg(src + p);
    }
    const uint32_t* wp = wsm + w * 2048 + lid;

    const int srow = tid >> 3, f0 = (tid & 7) * 16;
    const int wbase = srow * 68 + (f0 >> 1);

    float4 xr[4];
    {
        const float4* p = (const float4*)(g_seq1 +
            ((size_t)(blk * 64 + srow) * T1 + m0) * 128 + f0);
        #pragma unroll
        for (int i = 0; i < 4; i++) xr[i] = __ldg(p + i);
    }
    __syncthreads();

    for (int mi = 0; mi < 25; mi++) {
        const int m = m0 + mi;
        uint32_t* xth = (uint32_t*)(smc + PJ_X + (mi & 1) * 34816);
        uint32_t* xtl = xth + 4352;

        #pragma unroll
        for (int i = 0; i < 4; i++) {
            uint32_t h0, l0, h1, l1;
            split_pair(xr[i].x, xr[i].y, h0, l0);
            split_pair(xr[i].z, xr[i].w, h1, l1);
            xth[wbase + i * 2] = h0; xth[wbase + i * 2 + 1] = h1;
            xtl[wbase + i * 2] = l0; xtl[wbase + i * 2 + 1] = l1;
        }
        __syncthreads();

        if (mi < 24) {
            const float4* p = (const float4*)(g_seq1 +
                ((size_t)(blk * 64 + srow) * T1 + (m + 1)) * 128 + f0);
            #pragma unroll
            for (int i = 0; i < 4; i++) xr[i] = __ldg(p + i);
        }

        float cc[8][4];
        #pragma unroll
        for (int n = 0; n < 8; n++) {
            cc[n][0] = bv0; cc[n][1] = bv0; cc[n][2] = bv1; cc[n][3] = bv1;
        }
        for (int ks = 0; ks < 8; ks++) {
            uint32_t ah[4], al[4];
            #pragma unroll
            for (int r = 0; r < 4; r++) {
                ah[r] = wp[ks * 256 + r * 32];
                al[r] = wp[ks * 256 + 128 + r * 32];
            }
            #pragma unroll
            for (int n = 0; n < 8; n++) {
                int wd = (n * 8 + grp) * 68 + ks * 8 + tk;
                uint32_t bh0 = xth[wd], bh1 = xth[wd + 4];
                uint32_t bl0 = xtl[wd], bl1 = xtl[wd + 4];
                MMA(cc[n], ah, bh0, bh1);
                MMA(cc[n], ah, bl0, bl1);
                MMA(cc[n], al, bh0, bh1);
            }
        }
        __half* op = g_xg + ((((size_t)(d * 128 + blk) * 50 + m) * 16 + w) * 8) * 128 + lid * 4;
        #pragma unroll
        for (int n = 0; n < 8; n++) {
            __half2 a = __floats2half2_rn(cc[n][0], cc[n][1]);
            __half2 b = __floats2half2_rn(cc[n][2], cc[n][3]);
            uint2 v;
            v.x = *(uint32_t*)&a; v.y = *(uint32_t*)&b;
            *(uint2*)(op + n * 128) = v;
        }
        __syncthreads();
    }
}

// ===========================================================================
// k_layer2 v2: half-split software pipeline (round-15 validated) + fp16 xg
// ===========================================================================
#define L2_HTA 0            // A hi tile  1152 words
#define L2_HLA 4608         // A lo
#define L2_HTB 9216         // B hi
#define L2_HLB 13824        // B lo
#define L2_GA  18432        // 32*260*4 = 33280
#define L2_HBF 51712        // 32*68*4  = 8704
#define L2_OA  60416        // 64*100*4 = 25600
#define L2_SM  86016

__global__ __launch_bounds__(512, 1)
void k_layer2(const float* __restrict__ fc2_w, const float* __restrict__ fc2_b,
              float* __restrict__ out)
{
    extern __shared__ char smc[];
    uint32_t* hthA = (uint32_t*)(smc + L2_HTA);
    uint32_t* htlA = (uint32_t*)(smc + L2_HLA);
    uint32_t* hthB = (uint32_t*)(smc + L2_HTB);
    uint32_t* htlB = (uint32_t*)(smc + L2_HLB);
    float*    ga   = (float*)(smc + L2_GA);
    float*    hbf  = (float*)(smc + L2_HBF);
    float*    oa   = (float*)(smc + L2_OA);

    const int tid = threadIdx.x;
    const int w   = tid >> 5, lid = tid & 31;
    const int grp = lid >> 2, tk = lid & 3;
    const int j = tid & 63, q = tid >> 6;
    const int blk = blockIdx.x;
    const float fc2bv = __ldg(fc2_b);

    for (int d = 0; d < 2; d++) {
        const float fwa = __ldg(&fc2_w[d * 64 + lid]);
        const float fwb = __ldg(&fc2_w[d * 64 + 32 + lid]);

        uint32_t wa[32];
        {
            const uint32_t* hp = g_whhf + (d * 16 + w) * 4 * 256 + lid;
            #pragma unroll
            for (int ks = 0; ks < 4; ks++)
                #pragma unroll
                for (int tm = 0; tm < 2; tm++)
                    #pragma unroll
                    for (int r = 0; r < 4; r++)
                        wa[(ks * 2 + tm) * 4 + r] = __ldg(hp + (ks * 2 + tm) * 128 + r * 32);
        }

        __syncthreads();
        for (int p = tid; p < 4608; p += 512) hthA[p] = 0u;   // zeros all 4 tiles
        float c8A[4] = {0.f, 0.f, 0.f, 0.f};
        float c8B[4] = {0.f, 0.f, 0.f, 0.f};

        float xgA[16], xgB[16];
        {
            const int m0 = d ? 49 : 0;
            const __half* xp = g_xg + ((((size_t)(d * 128 + blk) * 50 + m0) * 16 + w) * 8) * 128 + lid * 4;
            #pragma unroll
            for (int nl = 0; nl < 4; nl++) {
                uint2 v = __ldg((const uint2*)(xp + nl * 128));
                float2 fa = __half22float2(*(__half2*)&v.x);
                float2 fb = __half22float2(*(__half2*)&v.y);
                xgA[nl * 4 + 0] = fa.x; xgA[nl * 4 + 1] = fa.y;
                xgA[nl * 4 + 2] = fb.x; xgA[nl * 4 + 3] = fb.y;
                uint2 u = __ldg((const uint2*)(xp + (4 + nl) * 128));
                float2 ua = __half22float2(*(__half2*)&u.x);
                float2 ub = __half22float2(*(__half2*)&u.y);
                xgB[nl * 4 + 0] = ua.x; xgB[nl * 4 + 1] = ua.y;
                xgB[nl * 4 + 2] = ub.x; xgB[nl * 4 + 3] = ub.y;
            }
        }
        __syncthreads();

        float cc[4][4];
        for (int tt = 0; tt < T2; tt++) {
            const int t  = d ? (T2 - 1 - tt) : tt;
            const int tp = d ? (t + 1) : (t - 1);
            const bool pf = (tt & 1) && (tt < 99);
            const int mn = pf ? (d ? ((t >> 1) - 1) : ((t >> 1) + 1)) : 0;
            const __half* xpn = g_xg + ((((size_t)(d * 128 + blk) * 50 + mn) * 16 + w) * 8) * 128 + lid * 4;

            // ---- Phase A: MMA half A (step tt) ----
            #pragma unroll
            for (int nl = 0; nl < 4; nl++)
                #pragma unroll
                for (int r = 0; r < 4; r++) cc[nl][r] = xgA[nl * 4 + r];
            if (pf) {
                #pragma unroll
                for (int nl = 0; nl < 4; nl++) {
                    uint2 v = __ldg((const uint2*)(xpn + nl * 128));
                    float2 fa = __half22float2(*(__half2*)&v.x);
                    float2 fb = __half22float2(*(__half2*)&v.y);
                    xgA[nl * 4 + 0] = fa.x; xgA[nl * 4 + 1] = fa.y;
                    xgA[nl * 4 + 2] = fb.x; xgA[nl * 4 + 3] = fb.y;
                }
            }
            #pragma unroll
            for (int ks = 0; ks < 4; ks++) {
                #pragma unroll
                for (int nl = 0; nl < 4; nl++) {
                    int wd = (nl * 8 + grp) * 36 + ks * 8 + tk;
                    uint32_t bh0 = hthA[wd], bh1 = hthA[wd + 4];
                    uint32_t bl0 = htlA[wd], bl1 = htlA[wd + 4];
                    MMA(cc[nl], &wa[(ks * 2 + 0) * 4], bh0, bh1);
                    MMA(cc[nl], &wa[(ks * 2 + 0) * 4], bl0, bl1);
                    MMA(cc[nl], &wa[(ks * 2 + 1) * 4], bh0, bh1);
                }
            }

            // ---- Phase B: epilogue half B (step tt-1) ----
            if (tt > 0) {
                #pragma unroll
                for (int si = 0; si < 4; si++) {
                    const int sl = q + si * 8;
                    float gi = ga[sl * 260 + j],       gf = ga[sl * 260 + 64 + j];
                    float gg = ga[sl * 260 + 128 + j], go = ga[sl * 260 + 192 + j];
                    float c = fmaf(sig_fast(gf), c8B[si], sig_fast(gi) * tanh_fast(gg));
                    c8B[si] = c;
                    float h = sig_fast(go) * tanh_fast(c);
                    hbf[sl * 68 + j] = h;
                    __nv_bfloat16 hh = __float2bfloat16_rn(h);
                    __nv_bfloat16 hl = __float2bfloat16_rn(h - __bfloat162float(hh));
                    ((__nv_bfloat16*)hthB)[sl * 72 + j] = hh;
                    ((__nv_bfloat16*)htlB)[sl * 72 + j] = hl;
                }
            }
            __syncthreads();   // bar1

            // ---- Phase C: fc2 half B (tt-1) + scatter A ----
            if (tt > 0) {
                #pragma unroll
                for (int si2 = 0; si2 < 2; si2++) {
                    const int sl = w * 2 + si2, s = 32 + sl;
                    float pm = hbf[sl * 68 + lid] * fwa + hbf[sl * 68 + 32 + lid] * fwb;
                    #pragma unroll
                    for (int o = 16; o > 0; o >>= 1)
                        pm += __shfl_down_sync(0xffffffffu, pm, o);
                    if (lid == 0) {
                        if (d == 0) oa[s * 100 + tp] = pm;
                        else out[(size_t)(blk * 64 + s) * T2 + tp] = ftanh_(oa[s * 100 + tp] + pm + fc2bv);
                    }
                }
            }
            #pragma unroll
            for (int nl = 0; nl < 4; nl++) {
                int sl0 = nl * 8 + 2 * tk, gcol = w * 16 + grp;
                ga[sl0 * 260 + gcol]           = cc[nl][0];
                ga[(sl0 + 1) * 260 + gcol]     = cc[nl][1];
                ga[sl0 * 260 + gcol + 8]       = cc[nl][2];
                ga[(sl0 + 1) * 260 + gcol + 8] = cc[nl][3];
            }
            __syncthreads();   // bar2

            // ---- Phase D: MMA half B (step tt) ----
            #pragma unroll
            for (int nl = 0; nl < 4; nl++)
                #pragma unroll
                for (int r = 0; r < 4; r++) cc[nl][r] = xgB[nl * 4 + r];
            if (pf) {
                #pragma unroll
                for (int nl = 0; nl < 4; nl++) {
                    uint2 u = __ldg((const uint2*)(xpn + (4 + nl) * 128));
                    float2 ua = __half22float2(*(__half2*)&u.x);
                    float2 ub = __half22float2(*(__half2*)&u.y);
                    xgB[nl * 4 + 0] = ua.x; xgB[nl * 4 + 1] = ua.y;
                    xgB[nl * 4 + 2] = ub.x; xgB[nl * 4 + 3] = ub.y;
                }
            }
            #pragma unroll
            for (int ks = 0; ks < 4; ks++) {
                #pragma unroll
                for (int nl = 0; nl < 4; nl++) {
                    int wd = (nl * 8 + grp) * 36 + ks * 8 + tk;
                    uint32_t bh0 = hthB[wd], bh1 = hthB[wd + 4];
                    uint32_t bl0 = htlB[wd], bl1 = htlB[wd + 4];
                    MMA(cc[nl], &wa[(ks * 2 + 0) * 4], bh0, bh1);
                    MMA(cc[nl], &wa[(ks * 2 + 0) * 4], bl0, bl1);
                    MMA(cc[nl], &wa[(ks * 2 + 1) * 4], bh0, bh1);
                }
            }

            // ---- Phase E: epilogue half A (step tt) ----
            #pragma unroll
            for (int si = 0; si < 4; si++) {
                const int sl = q + si * 8;
                float gi = ga[sl * 260 + j],       gf = ga[sl * 260 + 64 + j];
                float gg = ga[sl * 260 + 128 + j], go = ga[sl * 260 + 192 + j];
                float c = fmaf(sig_fast(gf), c8A[si], sig_fast(gi) * tanh_fast(gg));
                c8A[si] = c;
                float h = sig_fast(go) * tanh_fast(c);
                hbf[sl * 68 + j] = h;
                __nv_bfloat16 hh = __float2bfloat16_rn(h);
                __nv_bfloat16 hl = __float2bfloat16_rn(h - __bfloat162float(hh));
                ((__nv_bfloat16*)hthA)[sl * 72 + j] = hh;
                ((__nv_bfloat16*)htlA)[sl * 72 + j] = hl;
            }
            __syncthreads();   // bar3

            // ---- Phase F: fc2 half A (tt) + scatter B ----
            #pragma unroll
            for (int si2 = 0; si2 < 2; si2++) {
                const int sl = w * 2 + si2, s = sl;
                float pm = hbf[sl * 68 + lid] * fwa + hbf[sl * 68 + 32 + lid] * fwb;
                #pragma unroll
                for (int o = 16; o > 0; o >>= 1)
                    pm += __shfl_down_sync(0xffffffffu, pm, o);
                if (lid == 0) {
                    if (d == 0) oa[s * 100 + t] = pm;
                    else out[(size_t)(blk * 64 + s) * T2 + t] = ftanh_(oa[s * 100 + t] + pm + fc2bv);
                }
            }
            #pragma unroll
            for (int nl = 0; nl < 4; nl++) {
                int sl0 = nl * 8 + 2 * tk, gcol = w * 16 + grp;
                ga[sl0 * 260 + gcol]           = cc[nl][0];
                ga[(sl0 + 1) * 260 + gcol]     = cc[nl][1];
                ga[sl0 * 260 + gcol + 8]       = cc[nl][2];
                ga[(sl0 + 1) * 260 + gcol + 8] = cc[nl][3];
            }
            __syncthreads();   // bar4
        }

        // ---- drain: epilogue + fc2 for half B, last step ----
        {
            const int tl = d ? 0 : (T2 - 1);
            #pragma unroll
            for (int si = 0; si < 4; si++) {
                const int sl = q + si * 8;
                float gi = ga[sl * 260 + j],       gf = ga[sl * 260 + 64 + j];
                float gg = ga[sl * 260 + 128 + j], go = ga[sl * 260 + 192 + j];
                float c = fmaf(sig_fast(gf), c8B[si], sig_fast(gi) * tanh_fast(gg));
                c8B[si] = c;
                float h = sig_fast(go) * tanh_fast(c);
                hbf[sl * 68 + j] = h;
            }
            __syncthreads();
            #pragma unroll
            for (int si2 = 0; si2 < 2; si2++) {
                const int sl = w * 2 + si2, s = 32 + sl;
                float pm = hbf[sl * 68 + lid] * fwa + hbf[sl * 68 + 32 + lid] * fwb;
                #pragma unroll
                for (int o = 16; o > 0; o >>= 1)
                    pm += __shfl_down_sync(0xffffffffu, pm, o);
                if (lid == 0) {
                    if (d == 0) oa[s * 100 + tl] = pm;
                    else out[(size_t)(blk * 64 + s) * T2 + tl] = ftanh_(oa[s * 100 + tl] + pm + fc2bv);
                }
            }
            __syncthreads();
        }
    }
}

// ---------------------------------------------------------------------------
extern "C" void kernel_launch(void* const* d_in, const int* in_sizes, int n_in,
                              void* d_out, int out_size)
{
    const float* x    = (const float*)d_in[0];
    const float* fc1w = (const float*)d_in[1];
    const float* fc1b = (const float*)d_in[2];
    const float* r1wf = (const float*)d_in[3];
    const float* r1hf = (const float*)d_in[4];
    const float* r1bf = (const float*)d_in[5];
    const float* r1wb = (const float*)d_in[6];
    const float* r1hb = (const float*)d_in[7];
    const float* r1bb = (const float*)d_in[8];
    const float* r2wf = (const float*)d_in[9];
    const float* r2hf = (const float*)d_in[10];
    const float* r2bf = (const float*)d_in[11];
    const float* r2wb = (const float*)d_in[12];
    const float* r2hb = (const float*)d_in[13];
    const float* r2bb = (const float*)d_in[14];
    const float* fc2w = (const float*)d_in[15];
    const float* fc2b = (const float*)d_in[16];
    float* out = (float*)d_out;

    cudaFuncSetAttribute(k_layer1, cudaFuncAttributeMaxDynamicSharedMemorySize, L1_SM);
    cudaFuncSetAttribute(k_proj,   cudaFuncAttributeMaxDynamicSharedMemorySize, PJ_SM);
    cudaFuncSetAttribute(k_layer2, cudaFuncAttributeMaxDynamicSharedMemorySize, L2_SM);

    k_prep<<<64, 256>>>(r2wf, r2wb, r2hf, r2hb, r1hf, r1hb);
    k_layer1<<<128, 512, L1_SM>>>(x, fc1w, fc1b, r1wf, r1bf, r1wb, r1bb);
    k_proj<<<512, 512, PJ_SM>>>(r2bf, r2bb);
    k_layer2<<<128, 512, L2_SM>>>(fc2w, fc2b, out);
}